// round 1
// baseline (speedup 1.0000x reference)
#include <cuda_runtime.h>

#define BATCH 64
#define TT 1024
#define DD 512
#define HH 512
#define J4 2048           // 4*H
#define GRID_R 128        // recurrent grid (<=148 SMs -> co-resident, barrier safe)

// Scratch (static device memory; no runtime allocation)
__device__ float g_xwi[(size_t)BATCH * TT * J4];      // [m][j], m = b*T + t   (512 MB)
__device__ float g_whp[(size_t)GRID_R * 512 * 16];    // [bu][k][ut][g]        (4 MB)
__device__ float g_h[2][HH][BATCH];                   // double-buffered h, [u][b]
__device__ unsigned long long g_bar;

// ---------------------------------------------------------------------------
__global__ void reset_bar_kernel() { g_bar = 0ULL; }

// Repack Wh[k][g*512 + bu*4 + ut] -> g_whp[((bu*512 + k)*4 + ut)*4 + g]
__global__ void pack_wh_kernel(const float* __restrict__ Wh) {
    int d  = blockIdx.x * 256 + threadIdx.x;     // 1,048,576 total
    int g  = d & 3;
    int ut = (d >> 2) & 3;
    int k  = (d >> 4) & 511;
    int bu = d >> 13;
    g_whp[d] = Wh[(size_t)k * J4 + g * 512 + bu * 4 + ut];
}

// ---------------------------------------------------------------------------
// GEMM: g_xwi[m][j] = sum_k X[m][k]*Wi[k][j] + bias[j]
// tiles: BM=128, BN=64, BK=16; 256 threads; thread tile 8x4
__global__ __launch_bounds__(256) void gemm_xwi_kernel(
    const float* __restrict__ X, const float* __restrict__ Wi,
    const float* __restrict__ bias)
{
    __shared__ float sa[16 * 128];   // [k][m]
    __shared__ float sb[16 * 64];    // [k][j]

    const int nBase = blockIdx.x * 64;
    const int mBase = blockIdx.y * 128;
    const int t  = threadIdx.x;
    const int tx = t & 15;           // 16 n-tiles
    const int ty = t >> 4;           // 16 m-tiles

    // loader mapping
    const int am = t & 127;          // m row within tile
    const int ak = (t >> 7) * 8;     // k sub-block {0,8}
    const int bk = t >> 4;           // 0..15
    const int bj = (t & 15) * 4;

    float acc[8][4];
#pragma unroll
    for (int i = 0; i < 8; i++)
#pragma unroll
        for (int j = 0; j < 4; j++) acc[i][j] = 0.f;

    for (int k0 = 0; k0 < 512; k0 += 16) {
        float4 a0 = *(const float4*)&X[(size_t)(mBase + am) * DD + k0 + ak];
        float4 a1 = *(const float4*)&X[(size_t)(mBase + am) * DD + k0 + ak + 4];
        float4 bv = *(const float4*)&Wi[(size_t)(k0 + bk) * J4 + nBase + bj];
        __syncthreads();   // previous compute done
        sa[(ak + 0) * 128 + am] = a0.x;
        sa[(ak + 1) * 128 + am] = a0.y;
        sa[(ak + 2) * 128 + am] = a0.z;
        sa[(ak + 3) * 128 + am] = a0.w;
        sa[(ak + 4) * 128 + am] = a1.x;
        sa[(ak + 5) * 128 + am] = a1.y;
        sa[(ak + 6) * 128 + am] = a1.z;
        sa[(ak + 7) * 128 + am] = a1.w;
        *(float4*)&sb[bk * 64 + bj] = bv;
        __syncthreads();
#pragma unroll
        for (int k = 0; k < 16; k++) {
            float4 b4 = *(float4*)&sb[k * 64 + tx * 4];
            float4 aA = *(float4*)&sa[k * 128 + ty * 8];
            float4 aB = *(float4*)&sa[k * 128 + ty * 8 + 4];
            float a[8] = {aA.x, aA.y, aA.z, aA.w, aB.x, aB.y, aB.z, aB.w};
#pragma unroll
            for (int i = 0; i < 8; i++) {
                acc[i][0] += a[i] * b4.x;
                acc[i][1] += a[i] * b4.y;
                acc[i][2] += a[i] * b4.z;
                acc[i][3] += a[i] * b4.w;
            }
        }
    }

    float4 bb = *(const float4*)&bias[nBase + tx * 4];
#pragma unroll
    for (int i = 0; i < 8; i++) {
        float4 o;
        o.x = acc[i][0] + bb.x;
        o.y = acc[i][1] + bb.y;
        o.z = acc[i][2] + bb.z;
        o.w = acc[i][3] + bb.w;
        *(float4*)&g_xwi[(size_t)(mBase + ty * 8 + i) * J4 + nBase + tx * 4] = o;
    }
}

// ---------------------------------------------------------------------------
__device__ __forceinline__ void grid_barrier(unsigned long long target) {
    __threadfence();
    __syncthreads();
    if (threadIdx.x == 0) {
        atomicAdd(&g_bar, 1ULL);
        while (*(volatile unsigned long long*)&g_bar < target) {
            __nanosleep(40);
        }
        __threadfence();
    }
    __syncthreads();
}

__device__ __forceinline__ float sigf(float x) {
    return 1.0f / (1.0f + __expf(-x));
}

// Persistent scan. Block bu owns units [bu*4, bu*4+4), all gates, all batches.
// Thread: bt = batch-octet (8 batches), ut = unit-in-block, kq = k-split (8-way).
__global__ __launch_bounds__(256) void lstm_scan_kernel(
    const float* __restrict__ c0, const float* __restrict__ h0,
    float* __restrict__ out)
{
    __shared__ float sh[8192];   // h chunk [128][64]  /  sred [8][4][4][64]
    __shared__ float sw[2048];   // Wh chunk [128][4][4]
    __shared__ float csh[256];   // c state [4][64]

    const int bu = blockIdx.x;
    const int u_base = bu * 4;
    const int tid = threadIdx.x;
    const int bt = tid & 7;
    const int ut = (tid >> 3) & 3;
    const int kq = tid >> 5;
    const int au = tid >> 6;     // activation-phase unit 0..3
    const int ab = tid & 63;     // activation-phase batch

    // init c (shared, persistent) and h[0] (global, transposed [u][b])
    csh[au * 64 + ab] = c0[ab * HH + u_base + au];
    g_h[0][u_base + au][ab] = h0[ab * HH + u_base + au];
    grid_barrier((unsigned long long)GRID_R);

    float* ys = out + 2 * BATCH * HH;
    const float* whp_blk = g_whp + (size_t)bu * 512 * 16;

    for (int s = 0; s < TT; s++) {
        const int ph = s & 1;

        // prefetch x@Wi contribution for this thread's activation slot
        const float* xrow = g_xwi + ((size_t)ab * TT + s) * J4 + u_base + au;
        float xw0 = __ldg(xrow + 0 * 512);
        float xw1 = __ldg(xrow + 1 * 512);
        float xw2 = __ldg(xrow + 2 * 512);
        float xw3 = __ldg(xrow + 3 * 512);

        float acc[4][8];
#pragma unroll
        for (int g = 0; g < 4; g++)
#pragma unroll
            for (int b8 = 0; b8 < 8; b8++) acc[g][b8] = 0.f;

#pragma unroll 1
        for (int c = 0; c < 4; c++) {
            const int k0 = c * 128;
            // flat copies: h chunk (32KB) + Wh chunk (8KB)
            const float4* hs = (const float4*)&g_h[ph][k0][0];
            float4* shd = (float4*)sh;
#pragma unroll
            for (int r = 0; r < 8; r++) shd[tid + 256 * r] = hs[tid + 256 * r];
            const float4* wsrc = (const float4*)(whp_blk + (size_t)k0 * 16);
            float4* swd = (float4*)sw;
            swd[tid] = wsrc[tid];
            swd[tid + 256] = wsrc[tid + 256];
            __syncthreads();
#pragma unroll
            for (int kk2 = 0; kk2 < 16; kk2++) {
                const int kk = kq * 16 + kk2;
                float4 w  = *(float4*)&sw[(kk << 4) + (ut << 2)];
                float4 hA = *(float4*)&sh[(kk << 6) + (bt << 3)];
                float4 hB = *(float4*)&sh[(kk << 6) + (bt << 3) + 4];
                float hv[8] = {hA.x, hA.y, hA.z, hA.w, hB.x, hB.y, hB.z, hB.w};
                float wg[4] = {w.x, w.y, w.z, w.w};
#pragma unroll
                for (int g = 0; g < 4; g++)
#pragma unroll
                    for (int b8 = 0; b8 < 8; b8++)
                        acc[g][b8] += wg[g] * hv[b8];
            }
            __syncthreads();
        }

        // k-split reduction via shared: sred[kq][g][ut][b]
#pragma unroll
        for (int g = 0; g < 4; g++) {
            *(float4*)&sh[((kq * 4 + g) * 4 + ut) * 64 + bt * 8] =
                make_float4(acc[g][0], acc[g][1], acc[g][2], acc[g][3]);
            *(float4*)&sh[((kq * 4 + g) * 4 + ut) * 64 + bt * 8 + 4] =
                make_float4(acc[g][4], acc[g][5], acc[g][6], acc[g][7]);
        }
        __syncthreads();

        // activation: thread (au, ab)
        float si = xw0, sf = xw1, sg = xw2, so = xw3;
#pragma unroll
        for (int q = 0; q < 8; q++) {
            si += sh[((q * 4 + 0) * 4 + au) * 64 + ab];
            sf += sh[((q * 4 + 1) * 4 + au) * 64 + ab];
            sg += sh[((q * 4 + 2) * 4 + au) * 64 + ab];
            so += sh[((q * 4 + 3) * 4 + au) * 64 + ab];
        }
        float ig = sigf(si);
        float fg = sigf(sf);
        float gg = tanhf(sg);
        float og = sigf(so);
        float cold = csh[au * 64 + ab];
        float cnew = fg * cold + ig * gg;
        float hnew = og * tanhf(cnew);
        csh[au * 64 + ab] = cnew;

        g_h[ph ^ 1][u_base + au][ab] = hnew;
        ys[((size_t)ab * TT + s) * HH + u_base + au] = hnew;
        if (s == TT - 1) {
            out[ab * HH + u_base + au] = cnew;                 // cT
            out[BATCH * HH + ab * HH + u_base + au] = hnew;    // hT
        }

        if (s < TT - 1) {
            grid_barrier((unsigned long long)(s + 2) * GRID_R);
        }
    }
}

// ---------------------------------------------------------------------------
extern "C" void kernel_launch(void* const* d_in, const int* in_sizes, int n_in,
                              void* d_out, int out_size) {
    const float* x    = (const float*)d_in[0];   // [64][1024][512]
    const float* c0   = (const float*)d_in[1];   // [64][512]
    const float* h0   = (const float*)d_in[2];   // [64][512]
    const float* Wi   = (const float*)d_in[3];   // [512][2048]
    const float* Wh   = (const float*)d_in[4];   // [512][2048]
    const float* bias = (const float*)d_in[5];   // [2048]
    float* out = (float*)d_out;                  // cT | hT | ys

    pack_wh_kernel<<<4096, 256>>>(Wh);
    gemm_xwi_kernel<<<dim3(32, 512), 256>>>(x, Wi, bias);
    reset_bar_kernel<<<1, 1>>>();
    lstm_scan_kernel<<<GRID_R, 256>>>(c0, h0, out);
}